// round 13
// baseline (speedup 1.0000x reference)
#include <cuda_runtime.h>
#include <cuda_fp16.h>
#include <math.h>
#include <stdint.h>

// Problem constants
#define B_    4096
#define N_    32
#define H_    8
#define HID   512
#define M_TOT (B_ * N_)                         // 131072
#define OUT_OFF ((size_t)M_TOT * HID)           // 67108864 floats
#define ATTN_SIZE ((size_t)B_ * H_ * N_ * N_)   // 33554432

// Scratch (device globals: allocation-guard safe)
__device__ __half g_qkvh[(size_t)M_TOT * 3 * HID];  // [B*N, 1536] fp16
__device__ __half g_ctxh[(size_t)M_TOT * HID];      // [B*N, 512] fp16
__device__ __half g_xh[(size_t)M_TOT * HID];        // fp16 X
__device__ __half g_wqh[(size_t)3 * HID * HID];     // fp16 Wqkv
__device__ __half g_woh[(size_t)HID * HID];         // fp16 Wo
__device__ unsigned g_mask_bits[32];

// ---------------------------------------------------------------------------
// Mask normalizer (dtype-agnostic: 1-byte bool vs 4-byte int/float)
// ---------------------------------------------------------------------------
__global__ void normalize_mask_kernel(const void* maskp) {
    int i = threadIdx.x;  // 0..31
    const unsigned char* m8 = (const unsigned char*)maskp;
    unsigned diag_ok = __ballot_sync(0xffffffffu, m8[i * 33] != 0);
    unsigned bits = 0;
    if (diag_ok == 0xffffffffu) {
        for (int j = 0; j < 32; j++)
            bits |= (unsigned)(m8[i * 32 + j] != 0) << j;
    } else {
        const int* m32 = (const int*)maskp;
        for (int j = 0; j < 32; j++)
            bits |= (unsigned)(m32[i * 32 + j] != 0) << j;
    }
    g_mask_bits[i] = bits;
}

// ---------------------------------------------------------------------------
// fp32 -> fp16 conversion, 8 floats per thread
// ---------------------------------------------------------------------------
__global__ void cvt_f32_f16_kernel(const float* __restrict__ in,
                                   __half* __restrict__ out, int n8) {
    int i = blockIdx.x * blockDim.x + threadIdx.x;
    if (i >= n8) return;
    float4 a = ((const float4*)in)[2 * i];
    float4 b = ((const float4*)in)[2 * i + 1];
    __half2 h[4];
    h[0] = __floats2half2_rn(a.x, a.y);
    h[1] = __floats2half2_rn(a.z, a.w);
    h[2] = __floats2half2_rn(b.x, b.y);
    h[3] = __floats2half2_rn(b.z, b.w);
    ((uint4*)out)[i] = *(uint4*)h;
}

// ---------------------------------------------------------------------------
// PTX helpers
// ---------------------------------------------------------------------------
__device__ __forceinline__ void cp16(uint32_t dst, const void* src) {
    asm volatile("cp.async.cg.shared.global [%0], [%1], 16;\n"
                 :: "r"(dst), "l"(src));
}
__device__ __forceinline__ void ldsm_x4(uint32_t (&r)[4], uint32_t addr) {
    asm volatile("ldmatrix.sync.aligned.m8n8.x4.shared.b16 {%0,%1,%2,%3}, [%4];\n"
                 : "=r"(r[0]), "=r"(r[1]), "=r"(r[2]), "=r"(r[3]) : "r"(addr));
}
__device__ __forceinline__ void ldsm_x4_t(uint32_t (&r)[4], uint32_t addr) {
    asm volatile("ldmatrix.sync.aligned.m8n8.x4.trans.shared.b16 {%0,%1,%2,%3}, [%4];\n"
                 : "=r"(r[0]), "=r"(r[1]), "=r"(r[2]), "=r"(r[3]) : "r"(addr));
}
__device__ __forceinline__ void mma16816(float (&d)[4], const uint32_t (&a)[4],
                                         uint32_t b0, uint32_t b1) {
    asm volatile(
        "mma.sync.aligned.m16n8k16.row.col.f32.f16.f16.f32 "
        "{%0,%1,%2,%3}, {%4,%5,%6,%7}, {%8,%9}, {%0,%1,%2,%3};\n"
        : "+f"(d[0]), "+f"(d[1]), "+f"(d[2]), "+f"(d[3])
        : "r"(a[0]), "r"(a[1]), "r"(a[2]), "r"(a[3]), "r"(b0), "r"(b1));
}
__device__ __forceinline__ uint32_t packh2(float lo, float hi) {
    __half2 h = __floats2half2_rn(lo, hi);
    return *(uint32_t*)&h;
}

// ---------------------------------------------------------------------------
// FP16 tensor-core GEMM (TN): C[M,N] = A[M,K] @ W[N,K]^T + bias[N]
// 128x128x32 tile, 256 threads, 8 warps x (64x32), m16n8k16 + ldmatrix.x4.
// 5-stage cp.async pipeline (4-deep prefetch), ONE __syncthreads per K-iter.
// smem rows padded to 40 halves (80B): conflict-free LDSM, 16B-aligned.
// Requires M%128==0, N%128==0, K%32==0, K/32 >= 5.
// ---------------------------------------------------------------------------
#define BM 128
#define BN 128
#define BK 32
#define SROW 40                              // fp16 units per smem row
#define TILE_H (BM * SROW)                   // 5120 fp16 per A tile
#define STAGE_H (2 * TILE_H)                 // A + B per stage
#define NSTAGE 5
#define GEMM_SMEM (NSTAGE * STAGE_H * 2)     // 102400 bytes

template <bool HOUT>
__global__ __launch_bounds__(256, 2) void hmma_tn(
    const __half* __restrict__ A, const __half* __restrict__ W,
    const float* __restrict__ bias, void* __restrict__ Cv,
    int M, int N, int K)
{
    extern __shared__ __half sh[];
    const int tid = threadIdx.x;
    const int bm = blockIdx.y * BM;
    const int bn = blockIdx.x * BN;

    const uint32_t sbase = (uint32_t)__cvta_generic_to_shared(sh);

    // Loader: thread t copies 2x16B of A and 2x16B of B per stage.
    const int lrow = tid >> 1;                 // 0..127
    const int lk0 = (tid & 1) * 16;            // 0 or 16 (halves)
    const __half* Ag = A + (size_t)(bm + lrow) * K + lk0;
    const __half* Wg = W + (size_t)(bn + lrow) * K + lk0;

    auto issue = [&](int k0, int s) {
        uint32_t abuf = sbase + (uint32_t)(s * STAGE_H) * 2u;
        uint32_t bbuf = abuf + TILE_H * 2u;
        #pragma unroll
        for (int o = 0; o < 2; o++) {
            uint32_t soff = (uint32_t)(lrow * SROW + lk0 + o * 8) * 2u;
            cp16(abuf + soff, Ag + k0 + o * 8);
            cp16(bbuf + soff, Wg + k0 + o * 8);
        }
        asm volatile("cp.async.commit_group;\n");
    };

    const int warp = tid >> 5, lane = tid & 31;
    const int wm = (warp >> 2) * 64;
    const int wn = (warp & 3) * 32;
    const int qr = lane >> 2;
    const int qc = lane & 3;
    const int l15 = lane & 15;
    const int lhalf = lane >> 4;

    float acc[4][4][4];
    #pragma unroll
    for (int a = 0; a < 4; a++)
        #pragma unroll
        for (int b = 0; b < 4; b++)
            #pragma unroll
            for (int c = 0; c < 4; c++) acc[a][b][c] = 0.f;

    const int nIter = K / BK;     // >= 5 at all call sites (16)
    issue(0, 0);
    issue(BK, 1);
    issue(2 * BK, 2);
    issue(3 * BK, 3);

    for (int it = 0; it < nIter; it++) {
        // Groups committed after stage it = min(3, nIter-1-it); waiting to
        // that count guarantees stage it has fully arrived.
        const int pend = nIter - 1 - it;
        if (pend >= 3)      asm volatile("cp.async.wait_group 3;\n" ::: "memory");
        else if (pend == 2) asm volatile("cp.async.wait_group 2;\n" ::: "memory");
        else if (pend == 1) asm volatile("cp.async.wait_group 1;\n" ::: "memory");
        else                asm volatile("cp.async.wait_group 0;\n" ::: "memory");
        __syncthreads();
        // Slot (it+4)%5 was consumed at iter it-1; all threads are past it.
        if (it + 4 < nIter) issue((it + 4) * BK, (it + 4) % NSTAGE);

        const uint32_t abase = sbase + (uint32_t)((it % NSTAGE) * STAGE_H) * 2u;
        const uint32_t bbase = abase + TILE_H * 2u;

        #pragma unroll
        for (int ks = 0; ks < 2; ks++) {
            const int kcol = ks * 16 + lhalf * 8;
            uint32_t af[4][4];
            #pragma unroll
            for (int mt = 0; mt < 4; mt++)
                ldsm_x4(af[mt], abase +
                        (uint32_t)((wm + mt * 16 + l15) * SROW + kcol) * 2u);
            uint32_t bf[2][4];
            #pragma unroll
            for (int ng = 0; ng < 2; ng++)
                ldsm_x4(bf[ng], bbase +
                        (uint32_t)((wn + ng * 16 + l15) * SROW + kcol) * 2u);

            #pragma unroll
            for (int mt = 0; mt < 4; mt++)
                #pragma unroll
                for (int nt = 0; nt < 4; nt++)
                    mma16816(acc[mt][nt], af[mt],
                             bf[nt >> 1][(nt & 1)], bf[nt >> 1][(nt & 1) + 2]);
        }
    }

    #pragma unroll
    for (int nt = 0; nt < 4; nt++) {
        const int col = bn + wn + nt * 8 + qc * 2;
        const float2 bv = *(const float2*)(bias + col);
        #pragma unroll
        for (int mt = 0; mt < 4; mt++) {
            const int row = bm + wm + mt * 16 + qr;
            float2 v0 = { acc[mt][nt][0] + bv.x, acc[mt][nt][1] + bv.y };
            float2 v1 = { acc[mt][nt][2] + bv.x, acc[mt][nt][3] + bv.y };
            if (HOUT) {
                __half* C = (__half*)Cv;
                *(__half2*)(C + (size_t)row * N + col) =
                    __floats2half2_rn(v0.x, v0.y);
                *(__half2*)(C + (size_t)(row + 8) * N + col) =
                    __floats2half2_rn(v1.x, v1.y);
            } else {
                float* C = (float*)Cv;
                *(float2*)(C + (size_t)row * N + col) = v0;
                *(float2*)(C + (size_t)(row + 8) * N + col) = v1;
            }
        }
    }
}

// ---------------------------------------------------------------------------
// Tensor-core attention: one block per batch b, one warp per head h.
// QK^T and P*V on m16n8k16 mma; softmax fp32 in registers (shfl row-reduce).
// P stays in registers (S C-frag layout == PV A-frag layout). V via
// ldmatrix.trans. Per-warp smem: 2 tiles of 32x72 halves (K, and Q->V reuse).
// ---------------------------------------------------------------------------
#define ATS 72                              // halves per smem row
#define ATILE (32 * ATS)                    // 2304 halves per tile
#define AWARP (2 * ATILE)                   // per-warp halves
#define ATTN_SMEM (8 * AWARP * 2)           // 73728 bytes

__global__ __launch_bounds__(256) void attn_mma(
    const __half* __restrict__ qkv,
    float* __restrict__ attn_out,
    __half* __restrict__ ctx_out)
{
    extern __shared__ __half sha[];
    const int b = blockIdx.x;
    const int warp = threadIdx.x >> 5;    // head
    const int lane = threadIdx.x & 31;
    const int qr = lane >> 2, qc = lane & 3;
    const int l15 = lane & 15, lhalf = lane >> 4;

    __half* Qs = sha + warp * AWARP;      // later reused for V
    __half* Ks = Qs + ATILE;
    const uint32_t qsb = (uint32_t)__cvta_generic_to_shared(Qs);
    const uint32_t ksb = (uint32_t)__cvta_generic_to_shared(Ks);

    const __half* base = qkv + (size_t)b * 32 * 1536 + warp * 64;

    #pragma unroll 4
    for (int r = 0; r < 32; r++) {
        ((__half2*)(Qs + r * ATS))[lane] =
            ((const __half2*)(base + (size_t)r * 1536))[lane];
        ((__half2*)(Ks + r * ATS))[lane] =
            ((const __half2*)(base + (size_t)r * 1536 + 512))[lane];
    }
    __syncwarp();

    uint32_t qf[2][4][4];
    #pragma unroll
    for (int mt = 0; mt < 2; mt++)
        #pragma unroll
        for (int kt = 0; kt < 4; kt++)
            ldsm_x4(qf[mt][kt],
                    qsb + (uint32_t)((mt * 16 + l15) * ATS + kt * 16 + lhalf * 8) * 2u);
    uint32_t kf[4][2][4];
    #pragma unroll
    for (int kt = 0; kt < 4; kt++)
        #pragma unroll
        for (int ng = 0; ng < 2; ng++)
            ldsm_x4(kf[kt][ng],
                    ksb + (uint32_t)((ng * 16 + l15) * ATS + kt * 16 + lhalf * 8) * 2u);
    __syncwarp();

    #pragma unroll 4
    for (int r = 0; r < 32; r++)
        ((__half2*)(Qs + r * ATS))[lane] =
            ((const __half2*)(base + (size_t)r * 1536 + 1024))[lane];

    float S[2][4][4];
    #pragma unroll
    for (int mt = 0; mt < 2; mt++)
        #pragma unroll
        for (int nt = 0; nt < 4; nt++)
            #pragma unroll
            for (int c = 0; c < 4; c++) S[mt][nt][c] = 0.f;
    #pragma unroll
    for (int kt = 0; kt < 4; kt++)
        #pragma unroll
        for (int mt = 0; mt < 2; mt++)
            #pragma unroll
            for (int nt = 0; nt < 4; nt++)
                mma16816(S[mt][nt], qf[mt][kt],
                         kf[kt][nt >> 1][(nt & 1)], kf[kt][nt >> 1][(nt & 1) + 2]);

    #pragma unroll
    for (int mt = 0; mt < 2; mt++) {
        const int rlo = mt * 16 + qr;
        const unsigned blo = g_mask_bits[rlo];
        const unsigned bhi = g_mask_bits[rlo + 8];
        float mlo = -1e30f, mhi = -1e30f;
        #pragma unroll
        for (int nt = 0; nt < 4; nt++) {
            const int n0 = nt * 8 + qc * 2;
            S[mt][nt][0] = ((blo >> n0) & 1u)       ? S[mt][nt][0] * 0.125f : -1e9f;
            S[mt][nt][1] = ((blo >> (n0 + 1)) & 1u) ? S[mt][nt][1] * 0.125f : -1e9f;
            S[mt][nt][2] = ((bhi >> n0) & 1u)       ? S[mt][nt][2] * 0.125f : -1e9f;
            S[mt][nt][3] = ((bhi >> (n0 + 1)) & 1u) ? S[mt][nt][3] * 0.125f : -1e9f;
            mlo = fmaxf(mlo, fmaxf(S[mt][nt][0], S[mt][nt][1]));
            mhi = fmaxf(mhi, fmaxf(S[mt][nt][2], S[mt][nt][3]));
        }
        mlo = fmaxf(mlo, __shfl_xor_sync(0xffffffffu, mlo, 1));
        mlo = fmaxf(mlo, __shfl_xor_sync(0xffffffffu, mlo, 2));
        mhi = fmaxf(mhi, __shfl_xor_sync(0xffffffffu, mhi, 1));
        mhi = fmaxf(mhi, __shfl_xor_sync(0xffffffffu, mhi, 2));
        float slo = 0.f, shi = 0.f;
        #pragma unroll
        for (int nt = 0; nt < 4; nt++) {
            S[mt][nt][0] = __expf(S[mt][nt][0] - mlo);
            S[mt][nt][1] = __expf(S[mt][nt][1] - mlo);
            S[mt][nt][2] = __expf(S[mt][nt][2] - mhi);
            S[mt][nt][3] = __expf(S[mt][nt][3] - mhi);
            slo += S[mt][nt][0] + S[mt][nt][1];
            shi += S[mt][nt][2] + S[mt][nt][3];
        }
        slo += __shfl_xor_sync(0xffffffffu, slo, 1);
        slo += __shfl_xor_sync(0xffffffffu, slo, 2);
        shi += __shfl_xor_sync(0xffffffffu, shi, 1);
        shi += __shfl_xor_sync(0xffffffffu, shi, 2);
        const float ilo = 1.f / slo, ihi = 1.f / shi;
        #pragma unroll
        for (int nt = 0; nt < 4; nt++) {
            S[mt][nt][0] *= ilo; S[mt][nt][1] *= ilo;
            S[mt][nt][2] *= ihi; S[mt][nt][3] *= ihi;
        }
    }

    if (attn_out) {
        float* ao = attn_out + ((size_t)(b * 8 + warp) * 32) * 32;
        #pragma unroll
        for (int mt = 0; mt < 2; mt++) {
            const int rlo = mt * 16 + qr;
            #pragma unroll
            for (int nt = 0; nt < 4; nt++) {
                const int n0 = nt * 8 + qc * 2;
                *(float2*)(ao + rlo * 32 + n0) =
                    make_float2(S[mt][nt][0], S[mt][nt][1]);
                *(float2*)(ao + (rlo + 8) * 32 + n0) =
                    make_float2(S[mt][nt][2], S[mt][nt][3]);
            }
        }
    }

    uint32_t pf[2][2][4];   // [mt][kt2]
    #pragma unroll
    for (int mt = 0; mt < 2; mt++)
        #pragma unroll
        for (int k2 = 0; k2 < 2; k2++) {
            pf[mt][k2][0] = packh2(S[mt][2 * k2][0],     S[mt][2 * k2][1]);
            pf[mt][k2][1] = packh2(S[mt][2 * k2][2],     S[mt][2 * k2][3]);
            pf[mt][k2][2] = packh2(S[mt][2 * k2 + 1][0], S[mt][2 * k2 + 1][1]);
            pf[mt][k2][3] = packh2(S[mt][2 * k2 + 1][2], S[mt][2 * k2 + 1][3]);
        }
    __syncwarp();   // V tile fully written before ldsm

    #pragma unroll
    for (int dn = 0; dn < 2; dn++) {
        uint32_t vf[2][2][4];
        #pragma unroll
        for (int k2 = 0; k2 < 2; k2++)
            #pragma unroll
            for (int ng = 0; ng < 2; ng++)
                ldsm_x4_t(vf[k2][ng],
                          qsb + (uint32_t)((k2 * 16 + l15) * ATS +
                                           dn * 32 + ng * 16 + lhalf * 8) * 2u);
        float ctx[2][4][4];
        #pragma unroll
        for (int mt = 0; mt < 2; mt++)
            #pragma unroll
            for (int nt = 0; nt < 4; nt++)
                #pragma unroll
                for (int c = 0; c < 4; c++) ctx[mt][nt][c] = 0.f;
        #pragma unroll
        for (int k2 = 0; k2 < 2; k2++)
            #pragma unroll
            for (int mt = 0; mt < 2; mt++)
                #pragma unroll
                for (int nt = 0; nt < 4; nt++)
                    mma16816(ctx[mt][nt], pf[mt][k2],
                             vf[k2][nt >> 1][(nt & 1) * 2],
                             vf[k2][nt >> 1][(nt & 1) * 2 + 1]);
        #pragma unroll
        for (int mt = 0; mt < 2; mt++) {
            const int rlo = mt * 16 + qr;
            #pragma unroll
            for (int nt = 0; nt < 4; nt++) {
                const int d0 = warp * 64 + dn * 32 + nt * 8 + qc * 2;
                __half* c0 = ctx_out + (size_t)(b * 32 + rlo) * HID + d0;
                __half* c1 = ctx_out + (size_t)(b * 32 + rlo + 8) * HID + d0;
                *(__half2*)c0 = __floats2half2_rn(ctx[mt][nt][0], ctx[mt][nt][1]);
                *(__half2*)c1 = __floats2half2_rn(ctx[mt][nt][2], ctx[mt][nt][3]);
            }
        }
    }
}

// ---------------------------------------------------------------------------
extern "C" void kernel_launch(void* const* d_in, const int* in_sizes, int n_in,
                              void* d_out, int out_size)
{
    const float* X    = (const float*)d_in[0];  // [B,N,HID]
    const void*  mask = d_in[1];                // [N,N]
    const float* Wqkv = (const float*)d_in[2];  // [1536,512]
    const float* bqkv = (const float*)d_in[3];  // [1536]
    const float* Wo   = (const float*)d_in[4];  // [512,512]
    const float* bo   = (const float*)d_in[5];  // [512]
    float* out = (float*)d_out;

    cudaFuncSetAttribute(attn_mma,
                         cudaFuncAttributeMaxDynamicSharedMemorySize, ATTN_SMEM);
    cudaFuncSetAttribute(hmma_tn<true>,
                         cudaFuncAttributeMaxDynamicSharedMemorySize, GEMM_SMEM);
    cudaFuncSetAttribute(hmma_tn<false>,
                         cudaFuncAttributeMaxDynamicSharedMemorySize, GEMM_SMEM);

    __half *qkv_p = nullptr, *ctx_p = nullptr, *xh_p = nullptr;
    __half *wq_p = nullptr, *wo_p = nullptr;
    cudaGetSymbolAddress((void**)&qkv_p, g_qkvh);
    cudaGetSymbolAddress((void**)&ctx_p, g_ctxh);
    cudaGetSymbolAddress((void**)&xh_p, g_xh);
    cudaGetSymbolAddress((void**)&wq_p, g_wqh);
    cudaGetSymbolAddress((void**)&wo_p, g_woh);

    float* attn_p = ((size_t)out_size >= OUT_OFF + ATTN_SIZE) ? out + OUT_OFF
                                                              : nullptr;

    normalize_mask_kernel<<<1, 32>>>(mask);

    // Convert inputs/weights to fp16
    {
        int n8 = (int)(OUT_OFF / 8);                       // 8,388,608
        cvt_f32_f16_kernel<<<n8 / 256, 256>>>(X, xh_p, n8);
        int w8 = 3 * HID * HID / 8;
        cvt_f32_f16_kernel<<<(w8 + 255) / 256, 256>>>(Wqkv, wq_p, w8);
        int o8 = HID * HID / 8;
        cvt_f32_f16_kernel<<<(o8 + 255) / 256, 256>>>(Wo, wo_p, o8);
    }

    dim3 g1(3 * HID / BN, M_TOT / BM);   // (12, 1024)
    hmma_tn<true><<<g1, 256, GEMM_SMEM>>>(xh_p, wq_p, bqkv, qkv_p,
                                          M_TOT, 3 * HID, HID);

    attn_mma<<<B_, 256, ATTN_SMEM>>>(qkv_p, attn_p, ctx_p);

    dim3 g2(HID / BN, M_TOT / BM);       // (4, 1024)
    hmma_tn<false><<<g2, 256, GEMM_SMEM>>>(ctx_p, wo_p, bo, out,
                                           M_TOT, HID, HID);
}

// round 14
// speedup vs baseline: 1.5232x; 1.5232x over previous
#include <cuda_runtime.h>
#include <cuda_fp16.h>
#include <math.h>
#include <stdint.h>

// Problem constants
#define B_    4096
#define N_    32
#define H_    8
#define HID   512
#define M_TOT (B_ * N_)                         // 131072
#define OUT_OFF ((size_t)M_TOT * HID)           // 67108864 floats
#define ATTN_SIZE ((size_t)B_ * H_ * N_ * N_)   // 33554432

// Scratch (device globals: allocation-guard safe)
__device__ __half g_qkvh[(size_t)M_TOT * 3 * HID];  // [B*N, 1536] fp16
__device__ __half g_ctxh[(size_t)M_TOT * HID];      // [B*N, 512] fp16
__device__ __half g_xh[(size_t)M_TOT * HID];        // fp16 X
__device__ __half g_wqh[(size_t)3 * HID * HID];     // fp16 Wqkv
__device__ __half g_woh[(size_t)HID * HID];         // fp16 Wo
__device__ unsigned g_mask_bits[32];

// ---------------------------------------------------------------------------
// Mask normalizer (dtype-agnostic: 1-byte bool vs 4-byte int/float)
// ---------------------------------------------------------------------------
__global__ void normalize_mask_kernel(const void* maskp) {
    int i = threadIdx.x;  // 0..31
    const unsigned char* m8 = (const unsigned char*)maskp;
    unsigned diag_ok = __ballot_sync(0xffffffffu, m8[i * 33] != 0);
    unsigned bits = 0;
    if (diag_ok == 0xffffffffu) {
        for (int j = 0; j < 32; j++)
            bits |= (unsigned)(m8[i * 32 + j] != 0) << j;
    } else {
        const int* m32 = (const int*)maskp;
        for (int j = 0; j < 32; j++)
            bits |= (unsigned)(m32[i * 32 + j] != 0) << j;
    }
    g_mask_bits[i] = bits;
}

// ---------------------------------------------------------------------------
// Fused fp32 -> fp16 conversion of X, Wqkv, Wo in one launch.
// Each thread converts 8 floats.
// ---------------------------------------------------------------------------
#define N8_X  (int)(OUT_OFF / 8)                 // 8,388,608
#define N8_WQ (3 * HID * HID / 8)                // 98,304
#define N8_WO (HID * HID / 8)                    // 32,768
#define N8_TOT (N8_X + N8_WQ + N8_WO)

__global__ void cvt_all_kernel(const float* __restrict__ X,
                               const float* __restrict__ Wq,
                               const float* __restrict__ Wo,
                               __half* __restrict__ xh,
                               __half* __restrict__ wqh,
                               __half* __restrict__ woh) {
    int i = blockIdx.x * blockDim.x + threadIdx.x;
    if (i >= N8_TOT) return;
    const float* in;
    __half* out;
    int j = i;
    if (j < N8_X)                 { in = X;  out = xh;  }
    else if ((j -= N8_X) < N8_WQ) { in = Wq; out = wqh; }
    else       { j -= N8_WQ;        in = Wo; out = woh; }
    float4 a = ((const float4*)in)[2 * j];
    float4 b = ((const float4*)in)[2 * j + 1];
    __half2 h[4];
    h[0] = __floats2half2_rn(a.x, a.y);
    h[1] = __floats2half2_rn(a.z, a.w);
    h[2] = __floats2half2_rn(b.x, b.y);
    h[3] = __floats2half2_rn(b.z, b.w);
    ((uint4*)out)[j] = *(uint4*)h;
}

// ---------------------------------------------------------------------------
// PTX helpers
// ---------------------------------------------------------------------------
__device__ __forceinline__ void cp16(uint32_t dst, const void* src) {
    asm volatile("cp.async.cg.shared.global [%0], [%1], 16;\n"
                 :: "r"(dst), "l"(src));
}
__device__ __forceinline__ void ldsm_x4(uint32_t (&r)[4], uint32_t addr) {
    asm volatile("ldmatrix.sync.aligned.m8n8.x4.shared.b16 {%0,%1,%2,%3}, [%4];\n"
                 : "=r"(r[0]), "=r"(r[1]), "=r"(r[2]), "=r"(r[3]) : "r"(addr));
}
__device__ __forceinline__ void ldsm_x4_t(uint32_t (&r)[4], uint32_t addr) {
    asm volatile("ldmatrix.sync.aligned.m8n8.x4.trans.shared.b16 {%0,%1,%2,%3}, [%4];\n"
                 : "=r"(r[0]), "=r"(r[1]), "=r"(r[2]), "=r"(r[3]) : "r"(addr));
}
__device__ __forceinline__ void mma16816(float (&d)[4], const uint32_t (&a)[4],
                                         uint32_t b0, uint32_t b1) {
    asm volatile(
        "mma.sync.aligned.m16n8k16.row.col.f32.f16.f16.f32 "
        "{%0,%1,%2,%3}, {%4,%5,%6,%7}, {%8,%9}, {%0,%1,%2,%3};\n"
        : "+f"(d[0]), "+f"(d[1]), "+f"(d[2]), "+f"(d[3])
        : "r"(a[0]), "r"(a[1]), "r"(a[2]), "r"(a[3]), "r"(b0), "r"(b1));
}
__device__ __forceinline__ uint32_t packh2(float lo, float hi) {
    __half2 h = __floats2half2_rn(lo, hi);
    return *(uint32_t*)&h;
}

// ---------------------------------------------------------------------------
// FP16 tensor-core GEMM (TN): C[M,N] = A[M,K] @ W[N,K]^T + bias[N]
// 128x128x32 tile, 256 threads, 8 warps x (64x32), m16n8k16 + ldmatrix.x4.
// 3-stage cp.async pipeline, ONE __syncthreads per K-iter.  (R9-validated)
// ---------------------------------------------------------------------------
#define BM 128
#define BN 128
#define BK 32
#define SROW 40                              // fp16 units per smem row
#define TILE_H (BM * SROW)                   // 5120 fp16 per A tile
#define STAGE_H (2 * TILE_H)                 // A + B per stage
#define NSTAGE 3
#define GEMM_SMEM (NSTAGE * STAGE_H * 2)     // 61440 bytes

template <bool HOUT>
__global__ __launch_bounds__(256, 2) void hmma_tn(
    const __half* __restrict__ A, const __half* __restrict__ W,
    const float* __restrict__ bias, void* __restrict__ Cv,
    int M, int N, int K)
{
    extern __shared__ __half sh[];
    const int tid = threadIdx.x;
    const int bm = blockIdx.y * BM;
    const int bn = blockIdx.x * BN;

    const uint32_t sbase = (uint32_t)__cvta_generic_to_shared(sh);

    const int lrow = tid >> 1;                 // 0..127
    const int lk0 = (tid & 1) * 16;            // 0 or 16 (halves)
    const __half* Ag = A + (size_t)(bm + lrow) * K + lk0;
    const __half* Wg = W + (size_t)(bn + lrow) * K + lk0;

    auto issue = [&](int k0, int s) {
        uint32_t abuf = sbase + (uint32_t)(s * STAGE_H) * 2u;
        uint32_t bbuf = abuf + TILE_H * 2u;
        #pragma unroll
        for (int o = 0; o < 2; o++) {
            uint32_t soff = (uint32_t)(lrow * SROW + lk0 + o * 8) * 2u;
            cp16(abuf + soff, Ag + k0 + o * 8);
            cp16(bbuf + soff, Wg + k0 + o * 8);
        }
        asm volatile("cp.async.commit_group;\n");
    };

    const int warp = tid >> 5, lane = tid & 31;
    const int wm = (warp >> 2) * 64;
    const int wn = (warp & 3) * 32;
    const int qr = lane >> 2;
    const int qc = lane & 3;
    const int l15 = lane & 15;
    const int lhalf = lane >> 4;

    float acc[4][4][4];
    #pragma unroll
    for (int a = 0; a < 4; a++)
        #pragma unroll
        for (int b = 0; b < 4; b++)
            #pragma unroll
            for (int c = 0; c < 4; c++) acc[a][b][c] = 0.f;

    const int nIter = K / BK;
    issue(0, 0);
    issue(BK, 1);

    for (int it = 0; it < nIter; it++) {
        if (it + 1 < nIter) asm volatile("cp.async.wait_group 1;\n" ::: "memory");
        else                asm volatile("cp.async.wait_group 0;\n" ::: "memory");
        __syncthreads();
        if (it + 2 < nIter) issue((it + 2) * BK, (it + 2) % NSTAGE);

        const uint32_t abase = sbase + (uint32_t)((it % NSTAGE) * STAGE_H) * 2u;
        const uint32_t bbase = abase + TILE_H * 2u;

        #pragma unroll
        for (int ks = 0; ks < 2; ks++) {
            const int kcol = ks * 16 + lhalf * 8;
            uint32_t af[4][4];
            #pragma unroll
            for (int mt = 0; mt < 4; mt++)
                ldsm_x4(af[mt], abase +
                        (uint32_t)((wm + mt * 16 + l15) * SROW + kcol) * 2u);
            uint32_t bf[2][4];
            #pragma unroll
            for (int ng = 0; ng < 2; ng++)
                ldsm_x4(bf[ng], bbase +
                        (uint32_t)((wn + ng * 16 + l15) * SROW + kcol) * 2u);

            #pragma unroll
            for (int mt = 0; mt < 4; mt++)
                #pragma unroll
                for (int nt = 0; nt < 4; nt++)
                    mma16816(acc[mt][nt], af[mt],
                             bf[nt >> 1][(nt & 1)], bf[nt >> 1][(nt & 1) + 2]);
        }
    }

    #pragma unroll
    for (int nt = 0; nt < 4; nt++) {
        const int col = bn + wn + nt * 8 + qc * 2;
        const float2 bv = *(const float2*)(bias + col);
        #pragma unroll
        for (int mt = 0; mt < 4; mt++) {
            const int row = bm + wm + mt * 16 + qr;
            float2 v0 = { acc[mt][nt][0] + bv.x, acc[mt][nt][1] + bv.y };
            float2 v1 = { acc[mt][nt][2] + bv.x, acc[mt][nt][3] + bv.y };
            if (HOUT) {
                __half* C = (__half*)Cv;
                *(__half2*)(C + (size_t)row * N + col) =
                    __floats2half2_rn(v0.x, v0.y);
                *(__half2*)(C + (size_t)(row + 8) * N + col) =
                    __floats2half2_rn(v1.x, v1.y);
            } else {
                float* C = (float*)Cv;
                *(float2*)(C + (size_t)row * N + col) = v0;
                *(float2*)(C + (size_t)(row + 8) * N + col) = v1;
            }
        }
    }
}

// ---------------------------------------------------------------------------
// Tensor-core attention: one block per batch b, one warp per head h.
// QK^T and P*V on m16n8k16 mma; softmax fp32 in registers (shfl row-reduce).
// __launch_bounds__(256, 2): force reg cap so 2 CTAs/SM are resident
// (smem 73728B x 2 = 147KB fits; without min-blocks ptxas exceeds 128 regs
// and the kernel runs at 1 CTA/SM, latency-exposed).
// ---------------------------------------------------------------------------
#define ATS 72                              // halves per smem row
#define ATILE (32 * ATS)                    // 2304 halves per tile
#define AWARP (2 * ATILE)                   // per-warp halves
#define ATTN_SMEM (8 * AWARP * 2)           // 73728 bytes

__global__ __launch_bounds__(256, 2) void attn_mma(
    const __half* __restrict__ qkv,
    float* __restrict__ attn_out,
    __half* __restrict__ ctx_out)
{
    extern __shared__ __half sha[];
    const int b = blockIdx.x;
    const int warp = threadIdx.x >> 5;    // head
    const int lane = threadIdx.x & 31;
    const int qr = lane >> 2, qc = lane & 3;
    const int l15 = lane & 15, lhalf = lane >> 4;

    __half* Qs = sha + warp * AWARP;      // later reused for V
    __half* Ks = Qs + ATILE;
    const uint32_t qsb = (uint32_t)__cvta_generic_to_shared(Qs);
    const uint32_t ksb = (uint32_t)__cvta_generic_to_shared(Ks);

    const __half* base = qkv + (size_t)b * 32 * 1536 + warp * 64;

    #pragma unroll 4
    for (int r = 0; r < 32; r++) {
        ((__half2*)(Qs + r * ATS))[lane] =
            ((const __half2*)(base + (size_t)r * 1536))[lane];
        ((__half2*)(Ks + r * ATS))[lane] =
            ((const __half2*)(base + (size_t)r * 1536 + 512))[lane];
    }
    __syncwarp();

    uint32_t qf[2][4][4];
    #pragma unroll
    for (int mt = 0; mt < 2; mt++)
        #pragma unroll
        for (int kt = 0; kt < 4; kt++)
            ldsm_x4(qf[mt][kt],
                    qsb + (uint32_t)((mt * 16 + l15) * ATS + kt * 16 + lhalf * 8) * 2u);
    uint32_t kf[4][2][4];
    #pragma unroll
    for (int kt = 0; kt < 4; kt++)
        #pragma unroll
        for (int ng = 0; ng < 2; ng++)
            ldsm_x4(kf[kt][ng],
                    ksb + (uint32_t)((ng * 16 + l15) * ATS + kt * 16 + lhalf * 8) * 2u);
    __syncwarp();

    #pragma unroll 4
    for (int r = 0; r < 32; r++)
        ((__half2*)(Qs + r * ATS))[lane] =
            ((const __half2*)(base + (size_t)r * 1536 + 1024))[lane];

    float S[2][4][4];
    #pragma unroll
    for (int mt = 0; mt < 2; mt++)
        #pragma unroll
        for (int nt = 0; nt < 4; nt++)
            #pragma unroll
            for (int c = 0; c < 4; c++) S[mt][nt][c] = 0.f;
    #pragma unroll
    for (int kt = 0; kt < 4; kt++)
        #pragma unroll
        for (int mt = 0; mt < 2; mt++)
            #pragma unroll
            for (int nt = 0; nt < 4; nt++)
                mma16816(S[mt][nt], qf[mt][kt],
                         kf[kt][nt >> 1][(nt & 1)], kf[kt][nt >> 1][(nt & 1) + 2]);

    #pragma unroll
    for (int mt = 0; mt < 2; mt++) {
        const int rlo = mt * 16 + qr;
        const unsigned blo = g_mask_bits[rlo];
        const unsigned bhi = g_mask_bits[rlo + 8];
        float mlo = -1e30f, mhi = -1e30f;
        #pragma unroll
        for (int nt = 0; nt < 4; nt++) {
            const int n0 = nt * 8 + qc * 2;
            S[mt][nt][0] = ((blo >> n0) & 1u)       ? S[mt][nt][0] * 0.125f : -1e9f;
            S[mt][nt][1] = ((blo >> (n0 + 1)) & 1u) ? S[mt][nt][1] * 0.125f : -1e9f;
            S[mt][nt][2] = ((bhi >> n0) & 1u)       ? S[mt][nt][2] * 0.125f : -1e9f;
            S[mt][nt][3] = ((bhi >> (n0 + 1)) & 1u) ? S[mt][nt][3] * 0.125f : -1e9f;
            mlo = fmaxf(mlo, fmaxf(S[mt][nt][0], S[mt][nt][1]));
            mhi = fmaxf(mhi, fmaxf(S[mt][nt][2], S[mt][nt][3]));
        }
        mlo = fmaxf(mlo, __shfl_xor_sync(0xffffffffu, mlo, 1));
        mlo = fmaxf(mlo, __shfl_xor_sync(0xffffffffu, mlo, 2));
        mhi = fmaxf(mhi, __shfl_xor_sync(0xffffffffu, mhi, 1));
        mhi = fmaxf(mhi, __shfl_xor_sync(0xffffffffu, mhi, 2));
        float slo = 0.f, shi = 0.f;
        #pragma unroll
        for (int nt = 0; nt < 4; nt++) {
            S[mt][nt][0] = __expf(S[mt][nt][0] - mlo);
            S[mt][nt][1] = __expf(S[mt][nt][1] - mlo);
            S[mt][nt][2] = __expf(S[mt][nt][2] - mhi);
            S[mt][nt][3] = __expf(S[mt][nt][3] - mhi);
            slo += S[mt][nt][0] + S[mt][nt][1];
            shi += S[mt][nt][2] + S[mt][nt][3];
        }
        slo += __shfl_xor_sync(0xffffffffu, slo, 1);
        slo += __shfl_xor_sync(0xffffffffu, slo, 2);
        shi += __shfl_xor_sync(0xffffffffu, shi, 1);
        shi += __shfl_xor_sync(0xffffffffu, shi, 2);
        const float ilo = 1.f / slo, ihi = 1.f / shi;
        #pragma unroll
        for (int nt = 0; nt < 4; nt++) {
            S[mt][nt][0] *= ilo; S[mt][nt][1] *= ilo;
            S[mt][nt][2] *= ihi; S[mt][nt][3] *= ihi;
        }
    }

    if (attn_out) {
        float* ao = attn_out + ((size_t)(b * 8 + warp) * 32) * 32;
        #pragma unroll
        for (int mt = 0; mt < 2; mt++) {
            const int rlo = mt * 16 + qr;
            #pragma unroll
            for (int nt = 0; nt < 4; nt++) {
                const int n0 = nt * 8 + qc * 2;
                *(float2*)(ao + rlo * 32 + n0) =
                    make_float2(S[mt][nt][0], S[mt][nt][1]);
                *(float2*)(ao + (rlo + 8) * 32 + n0) =
                    make_float2(S[mt][nt][2], S[mt][nt][3]);
            }
        }
    }

    uint32_t pf[2][2][4];   // [mt][kt2]
    #pragma unroll
    for (int mt = 0; mt < 2; mt++)
        #pragma unroll
        for (int k2 = 0; k2 < 2; k2++) {
            pf[mt][k2][0] = packh2(S[mt][2 * k2][0],     S[mt][2 * k2][1]);
            pf[mt][k2][1] = packh2(S[mt][2 * k2][2],     S[mt][2 * k2][3]);
            pf[mt][k2][2] = packh2(S[mt][2 * k2 + 1][0], S[mt][2 * k2 + 1][1]);
            pf[mt][k2][3] = packh2(S[mt][2 * k2 + 1][2], S[mt][2 * k2 + 1][3]);
        }
    __syncwarp();   // V tile fully written before ldsm

    #pragma unroll
    for (int dn = 0; dn < 2; dn++) {
        uint32_t vf[2][2][4];
        #pragma unroll
        for (int k2 = 0; k2 < 2; k2++)
            #pragma unroll
            for (int ng = 0; ng < 2; ng++)
                ldsm_x4_t(vf[k2][ng],
                          qsb + (uint32_t)((k2 * 16 + l15) * ATS +
                                           dn * 32 + ng * 16 + lhalf * 8) * 2u);
        float ctx[2][4][4];
        #pragma unroll
        for (int mt = 0; mt < 2; mt++)
            #pragma unroll
            for (int nt = 0; nt < 4; nt++)
                #pragma unroll
                for (int c = 0; c < 4; c++) ctx[mt][nt][c] = 0.f;
        #pragma unroll
        for (int k2 = 0; k2 < 2; k2++)
            #pragma unroll
            for (int mt = 0; mt < 2; mt++)
                #pragma unroll
                for (int nt = 0; nt < 4; nt++)
                    mma16816(ctx[mt][nt], pf[mt][k2],
                             vf[k2][nt >> 1][(nt & 1) * 2],
                             vf[k2][nt >> 1][(nt & 1) * 2 + 1]);
        #pragma unroll
        for (int mt = 0; mt < 2; mt++) {
            const int rlo = mt * 16 + qr;
            #pragma unroll
            for (int nt = 0; nt < 4; nt++) {
                const int d0 = warp * 64 + dn * 32 + nt * 8 + qc * 2;
                __half* c0 = ctx_out + (size_t)(b * 32 + rlo) * HID + d0;
                __half* c1 = ctx_out + (size_t)(b * 32 + rlo + 8) * HID + d0;
                *(__half2*)c0 = __floats2half2_rn(ctx[mt][nt][0], ctx[mt][nt][1]);
                *(__half2*)c1 = __floats2half2_rn(ctx[mt][nt][2], ctx[mt][nt][3]);
            }
        }
    }
}

// ---------------------------------------------------------------------------
extern "C" void kernel_launch(void* const* d_in, const int* in_sizes, int n_in,
                              void* d_out, int out_size)
{
    const float* X    = (const float*)d_in[0];  // [B,N,HID]
    const void*  mask = d_in[1];                // [N,N]
    const float* Wqkv = (const float*)d_in[2];  // [1536,512]
    const float* bqkv = (const float*)d_in[3];  // [1536]
    const float* Wo   = (const float*)d_in[4];  // [512,512]
    const float* bo   = (const float*)d_in[5];  // [512]
    float* out = (float*)d_out;

    cudaFuncSetAttribute(attn_mma,
                         cudaFuncAttributeMaxDynamicSharedMemorySize, ATTN_SMEM);
    cudaFuncSetAttribute(hmma_tn<true>,
                         cudaFuncAttributeMaxDynamicSharedMemorySize, GEMM_SMEM);
    cudaFuncSetAttribute(hmma_tn<false>,
                         cudaFuncAttributeMaxDynamicSharedMemorySize, GEMM_SMEM);

    __half *qkv_p = nullptr, *ctx_p = nullptr, *xh_p = nullptr;
    __half *wq_p = nullptr, *wo_p = nullptr;
    cudaGetSymbolAddress((void**)&qkv_p, g_qkvh);
    cudaGetSymbolAddress((void**)&ctx_p, g_ctxh);
    cudaGetSymbolAddress((void**)&xh_p, g_xh);
    cudaGetSymbolAddress((void**)&wq_p, g_wqh);
    cudaGetSymbolAddress((void**)&wo_p, g_woh);

    float* attn_p = ((size_t)out_size >= OUT_OFF + ATTN_SIZE) ? out + OUT_OFF
                                                              : nullptr;

    normalize_mask_kernel<<<1, 32>>>(mask);

    // Fused fp16 conversion of X, Wqkv, Wo (one launch)
    cvt_all_kernel<<<(N8_TOT + 255) / 256, 256>>>(X, Wqkv, Wo,
                                                  xh_p, wq_p, wo_p);

    dim3 g1(3 * HID / BN, M_TOT / BM);   // (12, 1024)
    hmma_tn<true><<<g1, 256, GEMM_SMEM>>>(xh_p, wq_p, bqkv, qkv_p,
                                          M_TOT, 3 * HID, HID);

    attn_mma<<<B_, 256, ATTN_SMEM>>>(qkv_p, attn_p, ctx_p);

    dim3 g2(HID / BN, M_TOT / BM);       // (4, 1024)
    hmma_tn<false><<<g2, 256, GEMM_SMEM>>>(ctx_p, wo_p, bo, out,
                                           M_TOT, HID, HID);
}